// round 15
// baseline (speedup 1.0000x reference)
#include <cuda_runtime.h>
#include <cuda_fp16.h>
#include <cstdint>

// Problem shape (fixed by dataset)
constexpr int B = 1024;
constexpr int O = 256;
constexpr int D = 1024;

// Tiling: 64x32 block tile, 512 threads, TM=2 x TN=2 per thread
constexpr int BM = 64;
constexpr int BN = 32;
constexpr int BK = 64;
constexpr int TM = 2;
constexpr int TN = 2;
constexpr int XH  = BK + 8;   // fp16 tile row stride: 72 halves = 144B, 16B-aligned rows
constexpr int BQW = 68;       // btq row stride in uint32 (17 uint4 = 272B)

constexpr float ALPHA = 0.005f;
constexpr int NBLOCKS = (B / BM) * (O / BN);   // 128

// Grid barrier state (zero-init; g_count self-resets, g_flag monotonic across replays)
__device__ unsigned g_count = 0;
__device__ unsigned g_flag  = 0;

__device__ __forceinline__ void ldsm_x4(uint32_t& r0, uint32_t& r1, uint32_t& r2, uint32_t& r3,
                                        uint32_t addr) {
    asm volatile("ldmatrix.sync.aligned.m8n8.x4.shared.b16 {%0,%1,%2,%3}, [%4];"
                 : "=r"(r0), "=r"(r1), "=r"(r2), "=r"(r3) : "r"(addr));
}

__device__ __forceinline__ void ldsm_x2(uint32_t& r0, uint32_t& r1, uint32_t addr) {
    asm volatile("ldmatrix.sync.aligned.m8n8.x2.shared.b16 {%0,%1}, [%2];"
                 : "=r"(r0), "=r"(r1) : "r"(addr));
}

__device__ __forceinline__ void mma_f16(float d[4],
                                        uint32_t a0, uint32_t a1, uint32_t a2, uint32_t a3,
                                        uint32_t b0, uint32_t b1) {
    asm volatile(
        "mma.sync.aligned.m16n8k16.row.col.f32.f16.f16.f32 "
        "{%0,%1,%2,%3}, {%4,%5,%6,%7}, {%8,%9}, {%0,%1,%2,%3};"
        : "+f"(d[0]), "+f"(d[1]), "+f"(d[2]), "+f"(d[3])
        : "r"(a0), "r"(a1), "r"(a2), "r"(a3), "r"(b0), "r"(b1));
}

__device__ __forceinline__ __half2 u2h(uint32_t u) {
    return *reinterpret_cast<__half2*>(&u);
}

__global__ __launch_bounds__(512, 1) void CDR_fused_kernel(
    const float* __restrict__ x,
    const float* __restrict__ basis,
    float* __restrict__ xd)
{
    __shared__ __half    xh[BM][XH];          // fp16 x tile [m][k]
    __shared__ __half    bh[BN][XH];          // fp16 b tile [n][k]
    __shared__ uint32_t  btq[BK / 4][BQW];    // b packed: [kquad][npair*4 + slot]
    __shared__ float dots[BM][BN + 1];
    __shared__ float sSx[BM], sQx[BM], sSb[BN], sQb[BN];

    const int tid  = threadIdx.x;
    const int lane = tid & 31;
    const int w    = tid >> 5;        // warp 0-15
    const int wm   = w & 3;           // M16 block (0-3)
    const int wn   = w >> 2;          // N8 block (0-3)
    const int tx   = tid & 15;        // 16 across N
    const int ty   = tid >> 4;        // 32 across M
    const int bm   = blockIdx.x * BM;
    const int bn   = blockIdx.y * BN;

    const uint32_t xh_base = (uint32_t)__cvta_generic_to_shared(&xh[0][0]);
    const uint32_t bh_base = (uint32_t)__cvta_generic_to_shared(&bh[0][0]);
    const int a_row = wm * 16 + (lane & 15);
    const int a_col = (lane >> 4) * 8;
    const uint32_t a_addr = xh_base + (a_row * XH + a_col) * 2;
    const int b_row = wn * 8 + (lane & 7);        // lanes 0-15 supply x2 addresses
    const int b_col = ((lane >> 3) & 1) * 8;
    const uint32_t b_addr = bh_base + (b_row * XH + b_col) * 2;

    float accm[TM][TN];
#pragma unroll
    for (int i = 0; i < TM; i++)
#pragma unroll
        for (int j = 0; j < TN; j++) accm[i][j] = 0.0f;
    float dacc[4] = {};

    float sxa[2] = {}, qxa[2] = {};
    float sba = 0.0f, qba = 0.0f;

    // Prefetch chunk 0: x 2 float4/thread, basis 1 float4/thread
    float4 pvx[2], pvb;
#pragma unroll
    for (int t = 0; t < 2; t++) {
        int idx = tid + t * 512;
        pvx[t] = *reinterpret_cast<const float4*>(&x[(size_t)(bm + (idx >> 4)) * D + ((idx & 15) << 2)]);
    }
    pvb = *reinterpret_cast<const float4*>(&basis[(size_t)(bn + (tid >> 4)) * D + ((tid & 15) << 2)]);

#pragma unroll 1
    for (int chunk = 0; chunk < D / BK; chunk++) {
        // Store prefetched chunk (+ fp16 convert + row-sum accumulation)
#pragma unroll
        for (int t = 0; t < 2; t++) {
            int idx = tid + t * 512;
            int r = idx >> 4;
            int c = (idx & 15) << 2;
            float4 v = pvx[t];
            sxa[t] += (v.x + v.y) + (v.z + v.w);
            qxa[t] = fmaf(v.x, v.x, qxa[t]);
            qxa[t] = fmaf(v.y, v.y, qxa[t]);
            qxa[t] = fmaf(v.z, v.z, qxa[t]);
            qxa[t] = fmaf(v.w, v.w, qxa[t]);
            __half2 h0 = __floats2half2_rn(v.x, v.y);
            __half2 h1 = __floats2half2_rn(v.z, v.w);
            uint2 hp = make_uint2(*reinterpret_cast<uint32_t*>(&h0),
                                  *reinterpret_cast<uint32_t*>(&h1));
            *reinterpret_cast<uint2*>(&xh[r][c]) = hp;
        }
        {
            int r = tid >> 4;          // n (0..31)
            int c = (tid & 15) << 2;   // k
            float4 v = pvb;
            sba += (v.x + v.y) + (v.z + v.w);
            qba = fmaf(v.x, v.x, qba);
            qba = fmaf(v.y, v.y, qba);
            qba = fmaf(v.z, v.z, qba);
            qba = fmaf(v.w, v.w, qba);
            __half2 h0 = __floats2half2_rn(v.x, v.y);
            __half2 h1 = __floats2half2_rn(v.z, v.w);
            uint2 hp = make_uint2(*reinterpret_cast<uint32_t*>(&h0),
                                  *reinterpret_cast<uint32_t*>(&h1));
            *reinterpret_cast<uint2*>(&bh[r][c]) = hp;
            int kq = c >> 2, p = r >> 1, s = r & 1;
            btq[kq][p * 4 + s]     = hp.x;
            btq[kq][p * 4 + 2 + s] = hp.y;
        }
        __syncthreads();

        // Prefetch next chunk (overlapped with compute)
        if (chunk + 1 < D / BK) {
            int k0n = (chunk + 1) * BK;
#pragma unroll
            for (int t = 0; t < 2; t++) {
                int idx = tid + t * 512;
                pvx[t] = *reinterpret_cast<const float4*>(
                    &x[(size_t)(bm + (idx >> 4)) * D + k0n + ((idx & 15) << 2)]);
            }
            pvb = *reinterpret_cast<const float4*>(
                &basis[(size_t)(bn + (tid >> 4)) * D + k0n + ((tid & 15) << 2)]);
        }

        // Tensor path: each warp one m16n8 tile, 4 k16 steps
#pragma unroll
        for (int ks = 0; ks < 4; ks++) {
            uint32_t a0, a1, a2, a3, q0, q1;
            ldsm_x4(a0, a1, a2, a3, a_addr + ks * 32);
            ldsm_x2(q0, q1, b_addr + ks * 32);
            mma_f16(dacc, a0, a1, a2, a3, q0, q1);
        }

        // Scalar path: fp16x2 max+add, flush every 32 k
#pragma unroll
        for (int g = 0; g < 2; g++) {
            __half2 acch[TM][TN];
#pragma unroll
            for (int i = 0; i < TM; i++)
#pragma unroll
                for (int j = 0; j < TN; j++) acch[i][j] = __half2half2(__ushort_as_half(0));
#pragma unroll
            for (int h8 = 0; h8 < 4; h8++) {
                int kk = g * 32 + h8 * 8;
                uint4 Bq0 = *reinterpret_cast<const uint4*>(&btq[(kk >> 2)    ][tx * 4]);
                uint4 Bq1 = *reinterpret_cast<const uint4*>(&btq[(kk >> 2) + 1][tx * 4]);
#pragma unroll
                for (int i = 0; i < TM; i++) {
                    uint4 X = *reinterpret_cast<const uint4*>(&xh[ty * TM + i][kk]);
                    acch[i][0] = __hadd2(acch[i][0], __hmax2(u2h(X.x), u2h(Bq0.x)));
                    acch[i][1] = __hadd2(acch[i][1], __hmax2(u2h(X.x), u2h(Bq0.y)));
                    acch[i][0] = __hadd2(acch[i][0], __hmax2(u2h(X.y), u2h(Bq0.z)));
                    acch[i][1] = __hadd2(acch[i][1], __hmax2(u2h(X.y), u2h(Bq0.w)));
                    acch[i][0] = __hadd2(acch[i][0], __hmax2(u2h(X.z), u2h(Bq1.x)));
                    acch[i][1] = __hadd2(acch[i][1], __hmax2(u2h(X.z), u2h(Bq1.y)));
                    acch[i][0] = __hadd2(acch[i][0], __hmax2(u2h(X.w), u2h(Bq1.z)));
                    acch[i][1] = __hadd2(acch[i][1], __hmax2(u2h(X.w), u2h(Bq1.w)));
                }
            }
#pragma unroll
            for (int i = 0; i < TM; i++)
#pragma unroll
                for (int j = 0; j < TN; j++) {
                    float2 f = __half22float2(acch[i][j]);
                    accm[i][j] += f.x + f.y;
                }
        }
        __syncthreads();
    }

    // Row-sum reduction across 16 loader threads per row
#pragma unroll
    for (int off = 1; off < 16; off <<= 1) {
#pragma unroll
        for (int t = 0; t < 2; t++) {
            sxa[t] += __shfl_xor_sync(0xffffffffu, sxa[t], off);
            qxa[t] += __shfl_xor_sync(0xffffffffu, qxa[t], off);
        }
        sba += __shfl_xor_sync(0xffffffffu, sba, off);
        qba += __shfl_xor_sync(0xffffffffu, qba, off);
    }
    if ((tid & 15) == 0) {
        int rb = tid >> 4;   // 0..31
#pragma unroll
        for (int t = 0; t < 2; t++) { sSx[rb + 32 * t] = sxa[t]; sQx[rb + 32 * t] = qxa[t]; }
        sSb[rb] = sba; sQb[rb] = qba;
    }

    // mma fragment exchange (m16n8k16 C layout)
    {
        int r0 = wm * 16 + (lane >> 2);
        int c0 = wn * 8 + (lane & 3) * 2;
        dots[r0    ][c0    ] = dacc[0];
        dots[r0    ][c0 + 1] = dacc[1];
        dots[r0 + 8][c0    ] = dacc[2];
        dots[r0 + 8][c0 + 1] = dacc[3];
    }
    __syncthreads();

#pragma unroll
    for (int i = 0; i < TM; i++) {
        int ml = ty * TM + i;
        int m  = bm + ml;
        float sx = sSx[ml];
        float qx = sQx[ml];
#pragma unroll
        for (int j = 0; j < TN; j++) {
            int nl = tx * TN + j;
            int n  = bn + nl;
            float l1  = 2.0f * accm[i][j] - sx - sSb[nl];
            float l2s = qx - 2.0f * dots[ml][nl] + sQb[nl];
            xd[(size_t)m * O + n] = l1 + 0.5f * sqrtf(fmaxf(l2s, 0.0f));
        }
    }

    // ---- Grid barrier (128 blocks, 1/SM, all co-resident) ----
    __threadfence();
    __syncthreads();
    if (tid == 0) {
        unsigned f0 = atomicAdd(&g_flag, 0);
        unsigned t  = atomicAdd(&g_count, 1);
        if (t == NBLOCKS - 1) {
            g_count = 0;
            __threadfence();
            atomicAdd(&g_flag, 1);
        } else {
            while (atomicAdd(&g_flag, 0) == f0) { __nanosleep(64); }
        }
    }
    __syncthreads();

    // ---- Alpha pass: out = ALPHA*S - (1+ALPHA)*xd; warps 0-7 take one row each ----
    if (w < 8) {
        int bid = blockIdx.y * gridDim.x + blockIdx.x;   // 0..127
        int m   = bid * 8 + w;
        float4* row = reinterpret_cast<float4*>(xd + (size_t)m * O);
        float4 v0 = __ldcg(&row[lane]);
        float4 v1 = __ldcg(&row[lane + 32]);

        float s = (v0.x + v0.y) + (v0.z + v0.w) + (v1.x + v1.y) + (v1.z + v1.w);
#pragma unroll
        for (int off = 16; off > 0; off >>= 1)
            s += __shfl_xor_sync(0xffffffffu, s, off);

        const float cs = ALPHA * s;
        const float cv = -(1.0f + ALPHA);
        v0.x = fmaf(cv, v0.x, cs); v0.y = fmaf(cv, v0.y, cs);
        v0.z = fmaf(cv, v0.z, cs); v0.w = fmaf(cv, v0.w, cs);
        v1.x = fmaf(cv, v1.x, cs); v1.y = fmaf(cv, v1.y, cs);
        v1.z = fmaf(cv, v1.z, cs); v1.w = fmaf(cv, v1.w, cs);
        row[lane]      = v0;
        row[lane + 32] = v1;
    }
}

extern "C" void kernel_launch(void* const* d_in, const int* in_sizes, int n_in,
                              void* d_out, int out_size)
{
    const float* x     = (const float*)d_in[0];
    const float* basis = (const float*)d_in[1];
    float* out = (float*)d_out;

    dim3 grid(B / BM, O / BN);   // 16 x 8 = 128 blocks, all co-resident
    CDR_fused_kernel<<<grid, 512>>>(x, basis, out);
}

// round 16
// speedup vs baseline: 1.0703x; 1.0703x over previous
#include <cuda_runtime.h>
#include <cuda_fp16.h>
#include <cstdint>

// Problem shape (fixed by dataset)
constexpr int B = 1024;
constexpr int O = 256;
constexpr int D = 1024;

// Tiling: 64x32 block tile, 256 threads, TM=4 x TN=2 (LDS-minimal shape)
constexpr int BM = 64;
constexpr int BN = 32;
constexpr int BK = 64;
constexpr int TM = 4;
constexpr int TN = 2;
constexpr int XH  = BK + 8;   // fp16 tile row stride: 72 halves = 144B
constexpr int BQW = 68;       // btq row stride in uint32

constexpr float ALPHA = 0.005f;
constexpr int NBLOCKS = (B / BM) * (O / BN);   // 128
constexpr int NCHUNK  = D / BK;                // 16

// Per-buffer byte sizes for double buffering
constexpr int XH_BYTES  = BM * XH * 2;         // 9216
constexpr int BH_BYTES  = BN * XH * 2;         // 4608

// Grid barrier state (zero-init; g_count self-resets, g_flag monotonic across replays)
__device__ unsigned g_count = 0;
__device__ unsigned g_flag  = 0;

__device__ __forceinline__ void ldsm_x4(uint32_t& r0, uint32_t& r1, uint32_t& r2, uint32_t& r3,
                                        uint32_t addr) {
    asm volatile("ldmatrix.sync.aligned.m8n8.x4.shared.b16 {%0,%1,%2,%3}, [%4];"
                 : "=r"(r0), "=r"(r1), "=r"(r2), "=r"(r3) : "r"(addr));
}

__device__ __forceinline__ void mma_f16(float d[4],
                                        uint32_t a0, uint32_t a1, uint32_t a2, uint32_t a3,
                                        uint32_t b0, uint32_t b1) {
    asm volatile(
        "mma.sync.aligned.m16n8k16.row.col.f32.f16.f16.f32 "
        "{%0,%1,%2,%3}, {%4,%5,%6,%7}, {%8,%9}, {%0,%1,%2,%3};"
        : "+f"(d[0]), "+f"(d[1]), "+f"(d[2]), "+f"(d[3])
        : "r"(a0), "r"(a1), "r"(a2), "r"(a3), "r"(b0), "r"(b1));
}

__device__ __forceinline__ __half2 u2h(uint32_t u) {
    return *reinterpret_cast<__half2*>(&u);
}

__global__ __launch_bounds__(256, 1) void CDR_fused_kernel(
    const float* __restrict__ x,
    const float* __restrict__ basis,
    float* __restrict__ xd)
{
    __shared__ __half    xh[2][BM][XH];          // double-buffered fp16 x tile [m][k]
    __shared__ __half    bh[2][BN][XH];          // double-buffered fp16 b tile [n][k]
    __shared__ uint32_t  btq[2][BK / 4][BQW];    // double-buffered packed b
    __shared__ float dots[BM][BN + 1];
    __shared__ float sSx[BM], sQx[BM], sSb[BN], sQb[BN];

    const int tid  = threadIdx.x;
    const int lane = tid & 31;
    const int w    = tid >> 5;        // warp 0-7
    const int wm   = w & 3;
    const int wn   = w >> 2;
    const int tx   = tid & 15;
    const int ty   = tid >> 4;
    const int bm   = blockIdx.x * BM;
    const int bn   = blockIdx.y * BN;

    const uint32_t xh_base = (uint32_t)__cvta_generic_to_shared(&xh[0][0][0]);
    const uint32_t bh_base = (uint32_t)__cvta_generic_to_shared(&bh[0][0][0]);
    const int a_row = wm * 16 + (lane & 15);
    const int a_col = (lane >> 4) * 8;
    const uint32_t a_addr0 = xh_base + (a_row * XH + a_col) * 2;
    const int b_row = wn * 16 + (lane & 7) + ((lane >> 4) << 3);
    const int b_col = ((lane >> 3) & 1) * 8;
    const uint32_t b_addr0 = bh_base + (b_row * XH + b_col) * 2;

    float accm[TM][TN];
#pragma unroll
    for (int i = 0; i < TM; i++)
#pragma unroll
        for (int j = 0; j < TN; j++) accm[i][j] = 0.0f;
    float dacc[2][4] = {};

    float sxa[4] = {}, qxa[4] = {};
    float sba[2] = {}, qba[2] = {};

    // Loader geometry (fixed per thread)
    const int lrx = tid >> 4;            // x row base (0..15), rows lrx+16t
    const int lcx = (tid & 15) << 2;     // k col

    float4 pvx[4], pvb[2];

    // ---- Prologue: chunk 0 -> regs -> buf0; prefetch chunk 1 ----
#pragma unroll
    for (int t = 0; t < 4; t++)
        pvx[t] = *reinterpret_cast<const float4*>(&x[(size_t)(bm + lrx + 16 * t) * D + lcx]);
#pragma unroll
    for (int t = 0; t < 2; t++)
        pvb[t] = *reinterpret_cast<const float4*>(&basis[(size_t)(bn + lrx + 16 * t) * D + lcx]);

    // store chunk 0 into buffer 0
#pragma unroll
    for (int t = 0; t < 4; t++) {
        float4 v = pvx[t];
        int r = lrx + 16 * t;
        sxa[t] += (v.x + v.y) + (v.z + v.w);
        qxa[t] = fmaf(v.x, v.x, qxa[t]); qxa[t] = fmaf(v.y, v.y, qxa[t]);
        qxa[t] = fmaf(v.z, v.z, qxa[t]); qxa[t] = fmaf(v.w, v.w, qxa[t]);
        __half2 h0 = __floats2half2_rn(v.x, v.y);
        __half2 h1 = __floats2half2_rn(v.z, v.w);
        uint2 hp = make_uint2(*reinterpret_cast<uint32_t*>(&h0),
                              *reinterpret_cast<uint32_t*>(&h1));
        *reinterpret_cast<uint2*>(&xh[0][r][lcx]) = hp;
    }
#pragma unroll
    for (int t = 0; t < 2; t++) {
        float4 v = pvb[t];
        int r = lrx + 16 * t;
        sba[t] += (v.x + v.y) + (v.z + v.w);
        qba[t] = fmaf(v.x, v.x, qba[t]); qba[t] = fmaf(v.y, v.y, qba[t]);
        qba[t] = fmaf(v.z, v.z, qba[t]); qba[t] = fmaf(v.w, v.w, qba[t]);
        __half2 h0 = __floats2half2_rn(v.x, v.y);
        __half2 h1 = __floats2half2_rn(v.z, v.w);
        uint2 hp = make_uint2(*reinterpret_cast<uint32_t*>(&h0),
                              *reinterpret_cast<uint32_t*>(&h1));
        *reinterpret_cast<uint2*>(&bh[0][r][lcx]) = hp;
        int kq = lcx >> 2, p = r >> 1, s = r & 1;
        btq[0][kq][p * 4 + s]     = hp.x;
        btq[0][kq][p * 4 + 2 + s] = hp.y;
    }
    // prefetch chunk 1
#pragma unroll
    for (int t = 0; t < 4; t++)
        pvx[t] = *reinterpret_cast<const float4*>(&x[(size_t)(bm + lrx + 16 * t) * D + BK + lcx]);
#pragma unroll
    for (int t = 0; t < 2; t++)
        pvb[t] = *reinterpret_cast<const float4*>(&basis[(size_t)(bn + lrx + 16 * t) * D + BK + lcx]);
    __syncthreads();

#pragma unroll 1
    for (int chunk = 0; chunk < NCHUNK; chunk++) {
        const int cur = chunk & 1;
        const int nxt = cur ^ 1;
        const uint32_t a_addr = a_addr0 + cur * XH_BYTES;
        const uint32_t b_addr = b_addr0 + cur * BH_BYTES;

        // mma first half (ldsm latency overlaps the stores below)
#pragma unroll
        for (int ks = 0; ks < 2; ks++) {
            uint32_t a0, a1, a2, a3, q0, q1, q2, q3;
            ldsm_x4(a0, a1, a2, a3, a_addr + ks * 32);
            ldsm_x4(q0, q1, q2, q3, b_addr + ks * 32);
            mma_f16(dacc[0], a0, a1, a2, a3, q0, q1);
            mma_f16(dacc[1], a0, a1, a2, a3, q2, q3);
        }

        // Store prefetched chunk+1 into the other buffer (overlapped with compute)
        if (chunk + 1 < NCHUNK) {
#pragma unroll
            for (int t = 0; t < 4; t++) {
                float4 v = pvx[t];
                int r = lrx + 16 * t;
                sxa[t] += (v.x + v.y) + (v.z + v.w);
                qxa[t] = fmaf(v.x, v.x, qxa[t]); qxa[t] = fmaf(v.y, v.y, qxa[t]);
                qxa[t] = fmaf(v.z, v.z, qxa[t]); qxa[t] = fmaf(v.w, v.w, qxa[t]);
                __half2 h0 = __floats2half2_rn(v.x, v.y);
                __half2 h1 = __floats2half2_rn(v.z, v.w);
                uint2 hp = make_uint2(*reinterpret_cast<uint32_t*>(&h0),
                                      *reinterpret_cast<uint32_t*>(&h1));
                *reinterpret_cast<uint2*>(&xh[nxt][r][lcx]) = hp;
            }
#pragma unroll
            for (int t = 0; t < 2; t++) {
                float4 v = pvb[t];
                int r = lrx + 16 * t;
                sba[t] += (v.x + v.y) + (v.z + v.w);
                qba[t] = fmaf(v.x, v.x, qba[t]); qba[t] = fmaf(v.y, v.y, qba[t]);
                qba[t] = fmaf(v.z, v.z, qba[t]); qba[t] = fmaf(v.w, v.w, qba[t]);
                __half2 h0 = __floats2half2_rn(v.x, v.y);
                __half2 h1 = __floats2half2_rn(v.z, v.w);
                uint2 hp = make_uint2(*reinterpret_cast<uint32_t*>(&h0),
                                      *reinterpret_cast<uint32_t*>(&h1));
                *reinterpret_cast<uint2*>(&bh[nxt][r][lcx]) = hp;
                int kq = lcx >> 2, p = r >> 1, s = r & 1;
                btq[nxt][kq][p * 4 + s]     = hp.x;
                btq[nxt][kq][p * 4 + 2 + s] = hp.y;
            }
        }
        // Prefetch chunk+2 (LDG latency spans the rest of this chunk)
        if (chunk + 2 < NCHUNK) {
            int k0n = (chunk + 2) * BK;
#pragma unroll
            for (int t = 0; t < 4; t++)
                pvx[t] = *reinterpret_cast<const float4*>(
                    &x[(size_t)(bm + lrx + 16 * t) * D + k0n + lcx]);
#pragma unroll
            for (int t = 0; t < 2; t++)
                pvb[t] = *reinterpret_cast<const float4*>(
                    &basis[(size_t)(bn + lrx + 16 * t) * D + k0n + lcx]);
        }

        // Scalar g0 (k 0..31)
#pragma unroll
        for (int g = 0; g < 1; g++) {
            __half2 acch[TM][TN];
#pragma unroll
            for (int i = 0; i < TM; i++)
#pragma unroll
                for (int j = 0; j < TN; j++) acch[i][j] = __half2half2(__ushort_as_half(0));
#pragma unroll
            for (int h8 = 0; h8 < 4; h8++) {
                int kk = h8 * 8;
                uint4 Bq0 = *reinterpret_cast<const uint4*>(&btq[cur][(kk >> 2)    ][tx * 4]);
                uint4 Bq1 = *reinterpret_cast<const uint4*>(&btq[cur][(kk >> 2) + 1][tx * 4]);
#pragma unroll
                for (int i = 0; i < TM; i++) {
                    uint4 X = *reinterpret_cast<const uint4*>(&xh[cur][ty * TM + i][kk]);
                    acch[i][0] = __hadd2(acch[i][0], __hmax2(u2h(X.x), u2h(Bq0.x)));
                    acch[i][1] = __hadd2(acch[i][1], __hmax2(u2h(X.x), u2h(Bq0.y)));
                    acch[i][0] = __hadd2(acch[i][0], __hmax2(u2h(X.y), u2h(Bq0.z)));
                    acch[i][1] = __hadd2(acch[i][1], __hmax2(u2h(X.y), u2h(Bq0.w)));
                    acch[i][0] = __hadd2(acch[i][0], __hmax2(u2h(X.z), u2h(Bq1.x)));
                    acch[i][1] = __hadd2(acch[i][1], __hmax2(u2h(X.z), u2h(Bq1.y)));
                    acch[i][0] = __hadd2(acch[i][0], __hmax2(u2h(X.w), u2h(Bq1.z)));
                    acch[i][1] = __hadd2(acch[i][1], __hmax2(u2h(X.w), u2h(Bq1.w)));
                }
            }
#pragma unroll
            for (int i = 0; i < TM; i++)
#pragma unroll
                for (int j = 0; j < TN; j++) {
                    float2 f = __half22float2(acch[i][j]);
                    accm[i][j] += f.x + f.y;
                }
        }

        // mma second half
#pragma unroll
        for (int ks = 2; ks < 4; ks++) {
            uint32_t a0, a1, a2, a3, q0, q1, q2, q3;
            ldsm_x4(a0, a1, a2, a3, a_addr + ks * 32);
            ldsm_x4(q0, q1, q2, q3, b_addr + ks * 32);
            mma_f16(dacc[0], a0, a1, a2, a3, q0, q1);
            mma_f16(dacc[1], a0, a1, a2, a3, q2, q3);
        }

        // Scalar g1 (k 32..63)
        {
            __half2 acch[TM][TN];
#pragma unroll
            for (int i = 0; i < TM; i++)
#pragma unroll
                for (int j = 0; j < TN; j++) acch[i][j] = __half2half2(__ushort_as_half(0));
#pragma unroll
            for (int h8 = 0; h8 < 4; h8++) {
                int kk = 32 + h8 * 8;
                uint4 Bq0 = *reinterpret_cast<const uint4*>(&btq[cur][(kk >> 2)    ][tx * 4]);
                uint4 Bq1 = *reinterpret_cast<const uint4*>(&btq[cur][(kk >> 2) + 1][tx * 4]);
#pragma unroll
                for (int i = 0; i < TM; i++) {
                    uint4 X = *reinterpret_cast<const uint4*>(&xh[cur][ty * TM + i][kk]);
                    acch[i][0] = __hadd2(acch[i][0], __hmax2(u2h(X.x), u2h(Bq0.x)));
                    acch[i][1] = __hadd2(acch[i][1], __hmax2(u2h(X.x), u2h(Bq0.y)));
                    acch[i][0] = __hadd2(acch[i][0], __hmax2(u2h(X.y), u2h(Bq0.z)));
                    acch[i][1] = __hadd2(acch[i][1], __hmax2(u2h(X.y), u2h(Bq0.w)));
                    acch[i][0] = __hadd2(acch[i][0], __hmax2(u2h(X.z), u2h(Bq1.x)));
                    acch[i][1] = __hadd2(acch[i][1], __hmax2(u2h(X.z), u2h(Bq1.y)));
                    acch[i][0] = __hadd2(acch[i][0], __hmax2(u2h(X.w), u2h(Bq1.z)));
                    acch[i][1] = __hadd2(acch[i][1], __hmax2(u2h(X.w), u2h(Bq1.w)));
                }
            }
#pragma unroll
            for (int i = 0; i < TM; i++)
#pragma unroll
                for (int j = 0; j < TN; j++) {
                    float2 f = __half22float2(acch[i][j]);
                    accm[i][j] += f.x + f.y;
                }
        }
        __syncthreads();   // single sync per chunk (protects both buffers)
    }

    // Row-sum reduction across 16 loader threads per row
#pragma unroll
    for (int off = 1; off < 16; off <<= 1) {
#pragma unroll
        for (int t = 0; t < 4; t++) {
            sxa[t] += __shfl_xor_sync(0xffffffffu, sxa[t], off);
            qxa[t] += __shfl_xor_sync(0xffffffffu, qxa[t], off);
        }
#pragma unroll
        for (int t = 0; t < 2; t++) {
            sba[t] += __shfl_xor_sync(0xffffffffu, sba[t], off);
            qba[t] += __shfl_xor_sync(0xffffffffu, qba[t], off);
        }
    }
    if ((tid & 15) == 0) {
        int rb = tid >> 4;
#pragma unroll
        for (int t = 0; t < 4; t++) { sSx[rb + 16 * t] = sxa[t]; sQx[rb + 16 * t] = qxa[t]; }
#pragma unroll
        for (int t = 0; t < 2; t++) { sSb[rb + 16 * t] = sba[t]; sQb[rb + 16 * t] = qba[t]; }
    }

    // mma fragment exchange (m16n8k16 C layout)
    {
        int r0 = wm * 16 + (lane >> 2);
        int c0 = wn * 16 + (lane & 3) * 2;
#pragma unroll
        for (int t = 0; t < 2; t++) {
            dots[r0    ][c0 + t * 8    ] = dacc[t][0];
            dots[r0    ][c0 + t * 8 + 1] = dacc[t][1];
            dots[r0 + 8][c0 + t * 8    ] = dacc[t][2];
            dots[r0 + 8][c0 + t * 8 + 1] = dacc[t][3];
        }
    }
    __syncthreads();

#pragma unroll
    for (int i = 0; i < TM; i++) {
        int ml = ty * TM + i;
        int m  = bm + ml;
        float sx = sSx[ml];
        float qx = sQx[ml];
#pragma unroll
        for (int j = 0; j < TN; j++) {
            int nl = tx * TN + j;
            int n  = bn + nl;
            float l1  = 2.0f * accm[i][j] - sx - sSb[nl];
            float l2s = qx - 2.0f * dots[ml][nl] + sQb[nl];
            xd[(size_t)m * O + n] = l1 + 0.5f * sqrtf(fmaxf(l2s, 0.0f));
        }
    }

    // ---- Grid barrier (128 blocks, 1/SM, all co-resident) ----
    __threadfence();
    __syncthreads();
    if (tid == 0) {
        unsigned f0 = atomicAdd(&g_flag, 0);
        unsigned t  = atomicAdd(&g_count, 1);
        if (t == NBLOCKS - 1) {
            g_count = 0;
            __threadfence();
            atomicAdd(&g_flag, 1);
        } else {
            while (atomicAdd(&g_flag, 0) == f0) { __nanosleep(64); }
        }
    }
    __syncthreads();

    // ---- Alpha pass: out = ALPHA*S - (1+ALPHA)*xd; one warp per row ----
    {
        int bid = blockIdx.y * gridDim.x + blockIdx.x;   // 0..127
        int m   = bid * 8 + w;
        float4* row = reinterpret_cast<float4*>(xd + (size_t)m * O);
        float4 v0 = __ldcg(&row[lane]);
        float4 v1 = __ldcg(&row[lane + 32]);

        float s = (v0.x + v0.y) + (v0.z + v0.w) + (v1.x + v1.y) + (v1.z + v1.w);
#pragma unroll
        for (int off = 16; off > 0; off >>= 1)
            s += __shfl_xor_sync(0xffffffffu, s, off);

        const float cs = ALPHA * s;
        const float cv = -(1.0f + ALPHA);
        v0.x = fmaf(cv, v0.x, cs); v0.y = fmaf(cv, v0.y, cs);
        v0.z = fmaf(cv, v0.z, cs); v0.w = fmaf(cv, v0.w, cs);
        v1.x = fmaf(cv, v1.x, cs); v1.y = fmaf(cv, v1.y, cs);
        v1.z = fmaf(cv, v1.z, cs); v1.w = fmaf(cv, v1.w, cs);
        row[lane]      = v0;
        row[lane + 32] = v1;
    }
}

extern "C" void kernel_launch(void* const* d_in, const int* in_sizes, int n_in,
                              void* d_out, int out_size)
{
    const float* x     = (const float*)d_in[0];
    const float* basis = (const float*)d_in[1];
    float* out = (float*)d_out;

    dim3 grid(B / BM, O / BN);   // 16 x 8 = 128 blocks, all co-resident
    CDR_fused_kernel<<<grid, 256>>>(x, basis, out);
}